// round 8
// baseline (speedup 1.0000x reference)
#include <cuda_runtime.h>
#include <cstdint>

// Grouped submanifold sparse conv, N=400000, C_IN=C_OUT=64, GROUPS=4, K=27.
// R8: R7 (body list + dense consume + cp.async ring + smem acc) with the
// dominant L1 term attacked: weight reloads were 14.5 wf/body (32 wf per
// k-run / 2.2 bodies). VPW 8->16 raises reuse to ~3.65 bodies/k-run
// (-> 8.8 wf/body). Fits smem by: uint16 list entries (j<<5|k; neighbor
// index recomputed in fill from the L1-hot nb row) and an 8-slot ring
// (wave=4, depth=2; 128 gathers in flight per SM).

#define KOFF 27
#define WK   256                        // floats per (g,k)
#define WGRP (KOFF * WK)                // 6912
#define PG   (WGRP + 16)                // 6928 padded group stride
#define W_FLOATS (4 * PG)               // 27712
#define VPW  16
#define NWARPS 16
#define WAVE 4
#define NSLOT (2 * WAVE)                               // 8 slots x 256 B
#define ACC_F   W_FLOATS
#define ACC_PER_WARP (VPW * 32 * 2)                    // 1024 floats = 4 KB
#define RING_F  (ACC_F + NWARPS * ACC_PER_WARP)
#define RING_PER_WARP (NSLOT * 64)                     // 512 floats = 2 KB
#define LIST_F  (RING_F + NWARPS * RING_PER_WARP)
#define LIST_CAP 448                                   // >= VPW*27 = 432
#define SMEM_FLOATS (LIST_F + NWARPS * LIST_CAP / 2)   // uint16 entries
#define SMEM_BYTES (SMEM_FLOATS * 4)                   // 223488
#define FULL 0xffffffffu

#define CP_ASYNC16(dst, src) \
    asm volatile("cp.async.cg.shared.global [%0], [%1], 16;" \
                 :: "r"(dst), "l"(src) : "memory")
#define CP_COMMIT() asm volatile("cp.async.commit_group;" ::: "memory")
#define CP_WAIT1()  asm volatile("cp.async.wait_group 1;" ::: "memory")
#define CP_WAIT0()  asm volatile("cp.async.wait_group 0;" ::: "memory")

__global__ __launch_bounds__(512, 1)
void subm_conv_r8(const float* __restrict__ feat,
                  const float* __restrict__ weight,
                  const float* __restrict__ bias,
                  const int* __restrict__ nb,
                  float* __restrict__ out,
                  int N, int total_iters, int totwarps)
{
    extern __shared__ float sm[];
    for (int i = threadIdx.x; i < 4 * WGRP; i += 512) {
        int g = i / WGRP;
        sm[g * PG + (i - g * WGRP)] = weight[i];
    }
    __syncthreads();

    const int lane = threadIdx.x & 31;
    const int wid  = threadIdx.x >> 5;
    const int g    = lane >> 3;
    const int co0  = (lane & 7) * 2;
    const float bx = bias[2 * lane];
    const float by = bias[2 * lane + 1];
    const float* wgbase = sm + g * PG + co0;

    float2*   accw  = (float2*)(sm + ACC_F) + wid * (VPW * 32);
    float*    ringw = sm + RING_F + wid * RING_PER_WARP;
    uint16_t* lw    = (uint16_t*)(sm + LIST_F) + wid * LIST_CAP;
    const uint32_t ring_u32 = (uint32_t)__cvta_generic_to_shared(ringw);

    for (int it = blockIdx.x * NWARPS + wid; it < total_iters; it += totwarps) {
        const int vb = it * VPW;
        const int* nbrow = nb + (size_t)vb * KOFF;

        // ---- Phase A: activity mask, scan, emit (j,k) list (k-major) ----
        unsigned am = 0;
        #pragma unroll
        for (int j = 0; j < VPW; ++j) {
            int v = vb + j;
            int id = (lane < KOFF && v < N) ? nbrow[j * KOFF + lane] : -1;
            am |= (id >= 0 ? 1u : 0u) << j;
        }
        int pc = __popc(am);
        int s = pc;
        #pragma unroll
        for (int d = 1; d < 32; d <<= 1) {
            int t = __shfl_up_sync(FULL, s, d);
            if (lane >= d) s += t;
        }
        const int nb_total = __shfl_sync(FULL, s, 31);
        int pos = s - pc;                  // exclusive prefix over lanes (=k)
        unsigned em = am;
        while (em) {
            int j = __ffs(em) - 1; em &= em - 1;
            lw[pos++] = (uint16_t)((j << 5) | lane);
        }
        #pragma unroll
        for (int j = 0; j < VPW; ++j)
            accw[j * 32 + lane] = make_float2(bx, by);
        __syncwarp();

        // ---- async fill: wave of 4 bodies, 2 per instruction ----
        auto fill = [&](int wbase, int slotbase) {
            #pragma unroll
            for (int p = 0; p < WAVE; p += 2) {
                int bi = wbase + p + (lane >> 4);
                if (bi < nb_total) {
                    uint32_t e = lw[bi];
                    int jj = (int)(e >> 5), kk = (int)(e & 31u);
                    int ni = nbrow[jj * KOFF + kk];    // L1-hot broadcast
                    uint32_t dst = ring_u32
                                 + (uint32_t)(slotbase + p + (lane >> 4)) * 256u
                                 + (uint32_t)(lane & 15) * 16u;
                    const float* src = feat + (size_t)ni * 64 + (lane & 15) * 4;
                    CP_ASYNC16(dst, src);
                }
            }
            CP_COMMIT();
        };

        fill(0, 0);
        fill(WAVE, WAVE);

        // ---- Phase B: dense consume ----
        float2 w[16];
        int kcur = -1;
        for (int wbase = 0; wbase < nb_total; wbase += WAVE) {
            CP_WAIT1();
            __syncwarp();
            const int slotbase = ((wbase / WAVE) & 1) * WAVE;
            const int cend = (wbase + WAVE < nb_total) ? wbase + WAVE : nb_total;
            for (int i = wbase; i < cend; ++i) {
                const uint32_t e = lw[i];              // warp-uniform
                const int k = (int)(e & 31u);
                const int j = (int)(e >> 5);
                if (k != kcur) {                       // ~1 per 3.65 bodies
                    kcur = k;
                    const float2* wp = (const float2*)(wgbase + k * WK);
                    #pragma unroll
                    for (int q = 0; q < 16; ++q) w[q] = wp[q * 8];
                }
                const float4* sp = (const float4*)
                    (ringw + (slotbase + (i - wbase)) * 64 + g * 16);
                float4 fa = sp[0], fb = sp[1], fc = sp[2], fd = sp[3];
                float x  = fa.x * w[0].x;   float y  = fa.x * w[0].y;
                float xx = fa.y * w[1].x;   float yy = fa.y * w[1].y;
                x  += fa.z * w[2].x;   y  += fa.z * w[2].y;
                xx += fa.w * w[3].x;   yy += fa.w * w[3].y;
                x  += fb.x * w[4].x;   y  += fb.x * w[4].y;
                xx += fb.y * w[5].x;   yy += fb.y * w[5].y;
                x  += fb.z * w[6].x;   y  += fb.z * w[6].y;
                xx += fb.w * w[7].x;   yy += fb.w * w[7].y;
                x  += fc.x * w[8].x;   y  += fc.x * w[8].y;
                xx += fc.y * w[9].x;   yy += fc.y * w[9].y;
                x  += fc.z * w[10].x;  y  += fc.z * w[10].y;
                xx += fc.w * w[11].x;  yy += fc.w * w[11].y;
                x  += fd.x * w[12].x;  y  += fd.x * w[12].y;
                xx += fd.y * w[13].x;  yy += fd.y * w[13].y;
                x  += fd.z * w[14].x;  y  += fd.z * w[14].y;
                xx += fd.w * w[15].x;  yy += fd.w * w[15].y;
                x += xx; y += yy;
                float2* ap = accw + j * 32 + lane;     // same-lane RMW: ordered
                float2 a = *ap;
                a.x += x; a.y += y;
                *ap = a;
            }
            fill(wbase + 2 * WAVE, slotbase);
        }
        CP_WAIT0();
        __syncwarp();

        // ---- store 16 voxels x 64 channels ----
        #pragma unroll
        for (int j = 0; j < VPW; ++j) {
            int v = vb + j;
            if (v < N)
                ((float2*)(out + (size_t)v * 64))[lane] = accw[j * 32 + lane];
        }
        __syncwarp();
    }
}

extern "C" void kernel_launch(void* const* d_in, const int* in_sizes, int n_in,
                              void* d_out, int out_size)
{
    const float* feat   = (const float*)d_in[0];  // [N, 64]
    const float* weight = (const float*)d_in[1];  // [4, 27, 16, 16]
    const float* bias   = (const float*)d_in[2];  // [64]
    const int*   nb     = (const int*)d_in[3];    // [N, 27]
    float* out = (float*)d_out;

    int N = in_sizes[0] / 64;

    // Idempotent, enqueues no work; safe under graph capture.
    cudaFuncSetAttribute(subm_conv_r8,
                         cudaFuncAttributeMaxDynamicSharedMemorySize, SMEM_BYTES);

    const int blocks = 152;              // 1 CTA/SM (223.5 KB smem)
    const int threads = 512;             // 16 warps
    const int totwarps = blocks * NWARPS;
    int total_iters = (N + VPW - 1) / VPW;

    subm_conv_r8<<<blocks, threads, SMEM_BYTES>>>(feat, weight, bias, nb,
                                                  out, N, total_iters, totwarps);
    (void)n_in; (void)out_size;
}

// round 9
// speedup vs baseline: 1.3384x; 1.3384x over previous
#include <cuda_runtime.h>
#include <cuda_fp16.h>
#include <cstdint>

// Grouped submanifold sparse conv, N=400000, C_IN=C_OUT=64, GROUPS=4, K=27.
// R9 = R7 pipeline (16-slot ring, 8-body waves, LDS-only fill, smem acc,
// dense k-major body list) + R8's VPW=16 weight amortization, made to
// coexist by storing weights in smem as half2 (fp32 math after per-reload
// register conversion). Weight wf/body: 14.5 (R7) -> 4.4.
// List entries carry ni: ni<<9 | j<<5 | k (N < 2^19), so fill never touches
// global nb.

#define KOFF 27
#define VPW  16
#define NWARPS 16
#define WAVE 8
#define NSLOT (2 * WAVE)
// half2 weight area: [g][k][ci][cp]  cp = co/2 in 0..7, padded +8 per group
#define WGH   (KOFF * 128)              // 3456 half2 per group
#define PGH   (WGH + 8)                 // 3464 (8-word shift per group)
#define W_WORDS (4 * PGH)               // 13856 4-byte words
#define ACC_F   W_WORDS
#define ACC_PER_WARP (VPW * 32 * 2)     // 1024 floats = 4 KB
#define RING_F  (ACC_F + NWARPS * ACC_PER_WARP)
#define RING_PER_WARP (NSLOT * 64)      // 1024 floats = 4 KB
#define LIST_F  (RING_F + NWARPS * RING_PER_WARP)
#define LIST_CAP 432                    // = VPW * 27
#define SMEM_WORDS (LIST_F + NWARPS * LIST_CAP)
#define SMEM_BYTES (SMEM_WORDS * 4)     // 214,144 B
#define FULL 0xffffffffu

#define CP_ASYNC16(dst, src) \
    asm volatile("cp.async.cg.shared.global [%0], [%1], 16;" \
                 :: "r"(dst), "l"(src) : "memory")
#define CP_COMMIT() asm volatile("cp.async.commit_group;" ::: "memory")
#define CP_WAIT1()  asm volatile("cp.async.wait_group 1;" ::: "memory")
#define CP_WAIT0()  asm volatile("cp.async.wait_group 0;" ::: "memory")

__global__ __launch_bounds__(512, 1)
void subm_conv_r9(const float* __restrict__ feat,
                  const float* __restrict__ weight,
                  const float* __restrict__ bias,
                  const int* __restrict__ nb,
                  float* __restrict__ out,
                  int N, int total_iters, int totwarps)
{
    extern __shared__ float sm[];
    __half2* wh = (__half2*)sm;

    // Stage weights as half2 co-pairs: wh[g*PGH + k*128 + ci*8 + cp]
    for (int i = threadIdx.x; i < 4 * WGH; i += 512) {
        int g = i / WGH;
        float2 p = ((const float2*)weight)[i];      // co pairs are contiguous
        wh[g * PGH + (i - g * WGH)] = __float22half2_rn(p);
    }
    __syncthreads();

    const int lane = threadIdx.x & 31;
    const int wid  = threadIdx.x >> 5;
    const int g    = lane >> 3;          // group
    const int cp   = lane & 7;           // co-pair within group
    const float bx = bias[2 * lane];
    const float by = bias[2 * lane + 1];
    const __half2* whbase = wh + g * PGH + cp;

    float2*   accw  = (float2*)(sm + ACC_F) + wid * (VPW * 32);
    float*    ringw = sm + RING_F + wid * RING_PER_WARP;
    uint32_t* lw    = (uint32_t*)(sm + LIST_F) + wid * LIST_CAP;
    const uint32_t ring_u32 = (uint32_t)__cvta_generic_to_shared(ringw);

    for (int it = blockIdx.x * NWARPS + wid; it < total_iters; it += totwarps) {
        const int vb = it * VPW;
        const int* nbrow = nb + (size_t)vb * KOFF;

        // ---- Phase A: activity mask, prefix scan, emit list (k-major) ----
        unsigned am = 0;
        int idx[VPW];
        #pragma unroll
        for (int j = 0; j < VPW; ++j) {
            int v = vb + j;
            int id = (lane < KOFF && v < N) ? nbrow[j * KOFF + lane] : -1;
            idx[j] = id;
            am |= (id >= 0 ? 1u : 0u) << j;
        }
        int pc = __popc(am);
        int s = pc;
        #pragma unroll
        for (int d = 1; d < 32; d <<= 1) {
            int t = __shfl_up_sync(FULL, s, d);
            if (lane >= d) s += t;
        }
        const int nb_total = __shfl_sync(FULL, s, 31);
        int pos = s - pc;
        unsigned em = am;
        while (em) {
            int j = __ffs(em) - 1; em &= em - 1;
            lw[pos++] = ((uint32_t)idx[j] << 9) | (uint32_t)(j << 5)
                      | (uint32_t)lane;
        }
        #pragma unroll
        for (int j = 0; j < VPW; ++j)
            accw[j * 32 + lane] = make_float2(bx, by);
        __syncwarp();

        // ---- async fill: wave of 8 bodies, 2 per instruction, LDS-only ----
        auto fill = [&](int wbase, int slotbase) {
            #pragma unroll
            for (int p = 0; p < WAVE; p += 2) {
                int bi = wbase + p + (lane >> 4);
                if (bi < nb_total) {
                    uint32_t ni = lw[bi] >> 9;
                    uint32_t dst = ring_u32
                                 + (uint32_t)(slotbase + p + (lane >> 4)) * 256u
                                 + (uint32_t)(lane & 15) * 16u;
                    const float* src = feat + (size_t)ni * 64 + (lane & 15) * 4;
                    CP_ASYNC16(dst, src);
                }
            }
            CP_COMMIT();
        };

        fill(0, 0);
        fill(WAVE, WAVE);

        // ---- Phase B: dense consume ----
        float2 w[16];
        int kcur = -1;
        for (int wbase = 0; wbase < nb_total; wbase += WAVE) {
            CP_WAIT1();
            __syncwarp();
            const int slotbase = ((wbase / WAVE) & 1) * WAVE;
            const int cend = (wbase + WAVE < nb_total) ? wbase + WAVE : nb_total;
            for (int i = wbase; i < cend; ++i) {
                const uint32_t e = lw[i];               // warp-uniform
                const int k = (int)(e & 31u);
                const int j = (int)((e >> 5) & 15u);
                if (k != kcur) {                        // ~1 per 3.66 bodies
                    kcur = k;
                    const __half2* wp = whbase + k * 128;
                    #pragma unroll
                    for (int q = 0; q < 16; ++q)
                        w[q] = __half22float2(wp[q * 8]);  // 16 x LDS.32, cf
                }
                const float4* sp = (const float4*)
                    (ringw + (slotbase + (i - wbase)) * 64 + g * 16);
                float4 fa = sp[0], fb = sp[1], fc = sp[2], fd = sp[3];
                float x  = fa.x * w[0].x;   float y  = fa.x * w[0].y;
                float xx = fa.y * w[1].x;   float yy = fa.y * w[1].y;
                x  += fa.z * w[2].x;   y  += fa.z * w[2].y;
                xx += fa.w * w[3].x;   yy += fa.w * w[3].y;
                x  += fb.x * w[4].x;   y  += fb.x * w[4].y;
                xx += fb.y * w[5].x;   yy += fb.y * w[5].y;
                x  += fb.z * w[6].x;   y  += fb.z * w[6].y;
                xx += fb.w * w[7].x;   yy += fb.w * w[7].y;
                x  += fc.x * w[8].x;   y  += fc.x * w[8].y;
                xx += fc.y * w[9].x;   yy += fc.y * w[9].y;
                x  += fc.z * w[10].x;  y  += fc.z * w[10].y;
                xx += fc.w * w[11].x;  yy += fc.w * w[11].y;
                x  += fd.x * w[12].x;  y  += fd.x * w[12].y;
                xx += fd.y * w[13].x;  yy += fd.y * w[13].y;
                x  += fd.z * w[14].x;  y  += fd.z * w[14].y;
                xx += fd.w * w[15].x;  yy += fd.w * w[15].y;
                x += xx; y += yy;
                float2* ap = accw + j * 32 + lane;      // same-lane RMW
                float2 a = *ap;
                a.x += x; a.y += y;
                *ap = a;
            }
            fill(wbase + 2 * WAVE, slotbase);
        }
        CP_WAIT0();
        __syncwarp();

        // ---- store 16 voxels x 64 channels ----
        #pragma unroll
        for (int j = 0; j < VPW; ++j) {
            int v = vb + j;
            if (v < N)
                ((float2*)(out + (size_t)v * 64))[lane] = accw[j * 32 + lane];
        }
        __syncwarp();
    }
}

extern "C" void kernel_launch(void* const* d_in, const int* in_sizes, int n_in,
                              void* d_out, int out_size)
{
    const float* feat   = (const float*)d_in[0];  // [N, 64]
    const float* weight = (const float*)d_in[1];  // [4, 27, 16, 16]
    const float* bias   = (const float*)d_in[2];  // [64]
    const int*   nb     = (const int*)d_in[3];    // [N, 27]
    float* out = (float*)d_out;

    int N = in_sizes[0] / 64;

    // Idempotent, enqueues no work; safe under graph capture.
    cudaFuncSetAttribute(subm_conv_r9,
                         cudaFuncAttributeMaxDynamicSharedMemorySize, SMEM_BYTES);

    const int blocks = 152;              // 1 CTA/SM (214.1 KB smem)
    const int threads = 512;             // 16 warps
    const int totwarps = blocks * NWARPS;
    int total_iters = (N + VPW - 1) / VPW;

    subm_conv_r9<<<blocks, threads, SMEM_BYTES>>>(feat, weight, bias, nb,
                                                  out, N, total_iters, totwarps);
    (void)n_in; (void)out_size;
}